// round 1
// baseline (speedup 1.0000x reference)
#include <cuda_runtime.h>
#include <math.h>

#define D_TOT 25088      // 512*7*7
#define B_SZ  16
#define N_TOT 2000
#define NS    16         // n-splits for pass 2
#define PI2C  (3.14159f * 0.5f)

// ---- scratch (static device globals; no allocation) ----
__device__ float g_knr[B_SZ];                 // ||key_b||
__device__ float g_dots[B_SZ * N_TOT];        // raw dot products [b][n]
__device__ float g_mn2[N_TOT];                // ||m_n||^2
__device__ float g_wT[N_TOT * B_SZ];          // softmax weights, transposed [n][b]
__device__ float g_part[NS][B_SZ * D_TOT];    // pass-2 partial sums (~25.7 MB)

// ================= kernel A: key norms =================
__global__ void k_knorm(const float* __restrict__ key) {
    const int b = blockIdx.x;
    const float4* kp = reinterpret_cast<const float4*>(key + (size_t)b * D_TOT);
    float s = 0.f;
    for (int i = threadIdx.x; i < D_TOT / 4; i += blockDim.x) {
        float4 v = kp[i];
        s += v.x * v.x + v.y * v.y + v.z * v.z + v.w * v.w;
    }
    // block reduce
    __shared__ float red[32];
    #pragma unroll
    for (int o = 16; o > 0; o >>= 1) s += __shfl_xor_sync(0xffffffffu, s, o);
    if ((threadIdx.x & 31) == 0) red[threadIdx.x >> 5] = s;
    __syncthreads();
    if (threadIdx.x == 0) {
        float t = 0.f;
        for (int w = 0; w < (int)(blockDim.x >> 5); w++) t += red[w];
        g_knr[b] = sqrtf(t);
    }
}

// ================= kernel B: dots + memory norms =================
// Block handles 16 consecutive n. 8 warps = 2 n-groups (8 n each) x 4 b-warps (4 b each).
// Memory chunk [16][256] double-buffered in smem via cp.async; key read from L2.
__global__ void __launch_bounds__(256) k_pass1(const float* __restrict__ key,
                                               const float* __restrict__ mem) {
    __shared__ __align__(16) float sm[2][16 * 256];
    const int tid = threadIdx.x;
    const int wi = tid >> 5, ln = tid & 31;
    const int g = wi >> 2, q = wi & 3;
    const int b0 = q * 4, ng = g * 8;
    const int nb = blockIdx.x * 16;

    auto stage = [&](int c) {
        const int d0 = c << 8;
        #pragma unroll
        for (int k2 = 0; k2 < 4; k2++) {
            int fidx = tid + (k2 << 8);
            int nn = fidx >> 6, col4 = fidx & 63;
            const float* src = mem + (size_t)(nb + nn) * D_TOT + d0 + (col4 << 2);
            unsigned dst = (unsigned)__cvta_generic_to_shared(
                &sm[c & 1][(nn << 8) + (col4 << 2)]);
            asm volatile("cp.async.cg.shared.global [%0], [%1], 16;" ::
                         "r"(dst), "l"(src));
        }
    };

    stage(0); asm volatile("cp.async.commit_group;" ::: "memory");
    stage(1); asm volatile("cp.async.commit_group;" ::: "memory");

    float acc[4][8];
    #pragma unroll
    for (int i = 0; i < 4; i++)
        #pragma unroll
        for (int j = 0; j < 8; j++) acc[i][j] = 0.f;
    float na0 = 0.f, na1 = 0.f;

    const int NC = D_TOT / 256;  // 98
    for (int c = 0; c < NC; c++) {
        asm volatile("cp.async.wait_group 1;" ::: "memory");
        __syncthreads();
        const float* smc = sm[c & 1];
        #pragma unroll
        for (int s = 0; s < 2; s++) {
            const int col = (ln << 2) + (s << 7);
            const int dg = (c << 8) + col;
            float4 k4[4];
            #pragma unroll
            for (int bb = 0; bb < 4; bb++)
                k4[bb] = *reinterpret_cast<const float4*>(
                    key + (size_t)(b0 + bb) * D_TOT + dg);
            #pragma unroll
            for (int nn = 0; nn < 8; nn++) {
                float4 m4 = *reinterpret_cast<const float4*>(
                    smc + ((ng + nn) << 8) + col);
                #pragma unroll
                for (int bb = 0; bb < 4; bb++) {
                    float a = acc[bb][nn];
                    a = fmaf(m4.x, k4[bb].x, a);
                    a = fmaf(m4.y, k4[bb].y, a);
                    a = fmaf(m4.z, k4[bb].z, a);
                    a = fmaf(m4.w, k4[bb].w, a);
                    acc[bb][nn] = a;
                }
                if (nn == 2 * q) {
                    na0 = fmaf(m4.x, m4.x, na0); na0 = fmaf(m4.y, m4.y, na0);
                    na0 = fmaf(m4.z, m4.z, na0); na0 = fmaf(m4.w, m4.w, na0);
                }
                if (nn == 2 * q + 1) {
                    na1 = fmaf(m4.x, m4.x, na1); na1 = fmaf(m4.y, m4.y, na1);
                    na1 = fmaf(m4.z, m4.z, na1); na1 = fmaf(m4.w, m4.w, na1);
                }
            }
        }
        __syncthreads();
        if (c + 2 < NC) stage(c + 2);
        asm volatile("cp.async.commit_group;" ::: "memory");
    }

    // warp reductions over lanes (lanes partitioned D)
    #pragma unroll
    for (int bb = 0; bb < 4; bb++) {
        #pragma unroll
        for (int nn = 0; nn < 8; nn++) {
            float v = acc[bb][nn];
            #pragma unroll
            for (int o = 16; o > 0; o >>= 1) v += __shfl_xor_sync(0xffffffffu, v, o);
            if (ln == 0)
                g_dots[(size_t)(b0 + bb) * N_TOT + nb + ng + nn] = v;
        }
    }
    #pragma unroll
    for (int o = 16; o > 0; o >>= 1) {
        na0 += __shfl_xor_sync(0xffffffffu, na0, o);
        na1 += __shfl_xor_sync(0xffffffffu, na1, o);
    }
    if (ln == 0) {
        g_mn2[nb + ng + 2 * q]     = na0;
        g_mn2[nb + ng + 2 * q + 1] = na1;
    }
}

// ================= kernel C: softmax of tan(cos * PI/2) =================
__global__ void k_softmax() {
    const int b = blockIdx.x;
    __shared__ float lg[N_TOT];
    __shared__ float red[32];
    const float knr = g_knr[b];
    const int tid = threadIdx.x;

    float mx = -1e30f;
    for (int n = tid; n < N_TOT; n += blockDim.x) {
        float cs = g_dots[(size_t)b * N_TOT + n] / (knr * sqrtf(g_mn2[n]));
        float l = tanf(cs * PI2C);
        lg[n] = l;
        mx = fmaxf(mx, l);
    }
    #pragma unroll
    for (int o = 16; o > 0; o >>= 1) mx = fmaxf(mx, __shfl_xor_sync(0xffffffffu, mx, o));
    if ((tid & 31) == 0) red[tid >> 5] = mx;
    __syncthreads();
    if (tid == 0) {
        float t = -1e30f;
        for (int w = 0; w < (int)(blockDim.x >> 5); w++) t = fmaxf(t, red[w]);
        red[0] = t;
    }
    __syncthreads();
    mx = red[0];
    __syncthreads();

    float s = 0.f;
    for (int n = tid; n < N_TOT; n += blockDim.x) {
        float e = expf(lg[n] - mx);
        lg[n] = e;
        s += e;
    }
    #pragma unroll
    for (int o = 16; o > 0; o >>= 1) s += __shfl_xor_sync(0xffffffffu, s, o);
    if ((tid & 31) == 0) red[tid >> 5] = s;
    __syncthreads();
    if (tid == 0) {
        float t = 0.f;
        for (int w = 0; w < (int)(blockDim.x >> 5); w++) t += red[w];
        red[0] = t;
    }
    __syncthreads();
    const float inv = 1.f / red[0];
    for (int n = tid; n < N_TOT; n += blockDim.x)
        g_wT[(size_t)n * B_SZ + b] = lg[n] * inv;
}

// ================= kernel D: weighted read (partials over n-splits) =================
// grid (49, NS), 128 threads. Block covers 512 d, 125 n. acc = 16 float4 per thread.
__global__ void __launch_bounds__(128) k_read(const float* __restrict__ mem) {
    const int db = blockIdx.x, ns = blockIdx.y;
    const int n0 = ns * (N_TOT / NS);             // 125 n each
    const int tid = threadIdx.x;
    const int d = db * 512 + tid * 4;

    __shared__ __align__(16) float sw[(N_TOT / NS) * B_SZ];  // 125*16 floats
    for (int i = tid; i < (N_TOT / NS) * B_SZ; i += blockDim.x)
        sw[i] = g_wT[(size_t)n0 * B_SZ + i];
    __syncthreads();

    float4 a[16];
    #pragma unroll
    for (int i = 0; i < 16; i++) a[i] = make_float4(0.f, 0.f, 0.f, 0.f);

    const float* mp = mem + (size_t)n0 * D_TOT + d;

    #pragma unroll 4
    for (int n = 0; n < N_TOT / NS; n++) {
        float4 m4 = *reinterpret_cast<const float4*>(mp);
        mp += D_TOT;
        const float4* wv = reinterpret_cast<const float4*>(sw + (n << 4));
        float4 w0 = wv[0], w1 = wv[1], w2 = wv[2], w3 = wv[3];
        #define ACC4(ai, wb) \
            a[ai].x = fmaf(wb, m4.x, a[ai].x); a[ai].y = fmaf(wb, m4.y, a[ai].y); \
            a[ai].z = fmaf(wb, m4.z, a[ai].z); a[ai].w = fmaf(wb, m4.w, a[ai].w);
        ACC4(0,  w0.x) ACC4(1,  w0.y) ACC4(2,  w0.z) ACC4(3,  w0.w)
        ACC4(4,  w1.x) ACC4(5,  w1.y) ACC4(6,  w1.z) ACC4(7,  w1.w)
        ACC4(8,  w2.x) ACC4(9,  w2.y) ACC4(10, w2.z) ACC4(11, w2.w)
        ACC4(12, w3.x) ACC4(13, w3.y) ACC4(14, w3.z) ACC4(15, w3.w)
        #undef ACC4
    }

    float* pp = g_part[ns];
    #pragma unroll
    for (int b = 0; b < 16; b++)
        *reinterpret_cast<float4*>(pp + (size_t)b * D_TOT + d) = a[b];
}

// ================= kernel E: sum partials =================
__global__ void k_final(float* __restrict__ out) {
    const int i = blockIdx.x * blockDim.x + threadIdx.x;  // float4 index
    float4 s = make_float4(0.f, 0.f, 0.f, 0.f);
    #pragma unroll
    for (int p = 0; p < NS; p++) {
        float4 v = reinterpret_cast<const float4*>(g_part[p])[i];
        s.x += v.x; s.y += v.y; s.z += v.z; s.w += v.w;
    }
    reinterpret_cast<float4*>(out)[i] = s;
}

// ================= launcher =================
extern "C" void kernel_launch(void* const* d_in, const int* in_sizes, int n_in,
                              void* d_out, int out_size) {
    const float* key = (const float*)d_in[0];
    const float* mem = (const float*)d_in[1];
    if (n_in >= 2 && in_sizes[0] > in_sizes[1]) {  // defensive: key is the small one
        const float* t = key; key = mem; mem = t;
    }
    k_knorm<<<B_SZ, 256>>>(key);
    k_pass1<<<N_TOT / 16, 256>>>(key, mem);
    k_softmax<<<B_SZ, 256>>>();
    k_read<<<dim3(D_TOT / 512, NS), 128>>>(mem);
    k_final<<<(B_SZ * D_TOT / 4) / 256, 256>>>((float*)d_out);
}

// round 2
// speedup vs baseline: 1.0217x; 1.0217x over previous
#include <cuda_runtime.h>
#include <math.h>

#define D_TOT 25088      // 512*7*7
#define B_SZ  16
#define N_TOT 2000
#define NS    16         // n-splits for pass 2
#define DQ    7          // d-segments for pass 1
#define CHK   128        // floats per pass-1 chunk
#define NCHK  28         // chunks per d-segment (7*28*128 = 25088)
#define PI2C  (3.14159f * 0.5f)

// ---- scratch (static device globals; no allocation) ----
__device__ float g_knr[B_SZ];                     // ||key_b||
__device__ float g_dotp[DQ][B_SZ][N_TOT];         // partial dots per d-segment
__device__ float g_mn2p[DQ][N_TOT];               // partial ||m_n||^2
__device__ float g_wT[N_TOT * B_SZ];              // softmax weights, transposed [n][b]
__device__ float g_part[NS][B_SZ * D_TOT];        // pass-2 partial sums

// ---- packed fp32x2 helpers (Blackwell FFMA2 path) ----
__device__ __forceinline__ void ffma2(unsigned long long& acc,
                                      unsigned long long a, unsigned long long b) {
    asm("fma.rn.f32x2 %0, %1, %2, %0;" : "+l"(acc) : "l"(a), "l"(b));
}
__device__ __forceinline__ unsigned long long dup2(float v) {
    unsigned long long r;
    asm("mov.b64 %0, {%1, %1};" : "=l"(r) : "r"(__float_as_uint(v)));
    return r;
}
__device__ __forceinline__ float psum2(unsigned long long v) {
    float lo, hi;
    asm("mov.b64 {%0, %1}, %2;" : "=f"(lo), "=f"(hi) : "l"(v));
    return lo + hi;
}

// ================= kernel A: key norms =================
__global__ void k_knorm(const float* __restrict__ key) {
    const int b = blockIdx.x;
    const float4* kp = reinterpret_cast<const float4*>(key + (size_t)b * D_TOT);
    float s = 0.f;
    for (int i = threadIdx.x; i < D_TOT / 4; i += blockDim.x) {
        float4 v = kp[i];
        s += v.x * v.x + v.y * v.y + v.z * v.z + v.w * v.w;
    }
    __shared__ float red[32];
    #pragma unroll
    for (int o = 16; o > 0; o >>= 1) s += __shfl_xor_sync(0xffffffffu, s, o);
    if ((threadIdx.x & 31) == 0) red[threadIdx.x >> 5] = s;
    __syncthreads();
    if (threadIdx.x == 0) {
        float t = 0.f;
        for (int w = 0; w < (int)(blockDim.x >> 5); w++) t += red[w];
        g_knr[b] = sqrtf(t);
    }
}

// ================= kernel B: dots + memory norms (pass 1) =================
// grid (125, 7): block = (16 n) x (3584 d segment). 256 threads = 8 warps:
// q = wi&3 -> 4 b each; g = wi>>2 -> 8 n each. Lanes partition the 128-d chunk.
// 4-stage cp.async pipeline, FFMA2 inner loop.
__global__ void __launch_bounds__(256) k_pass1(const float* __restrict__ key,
                                               const float* __restrict__ mem) {
    __shared__ __align__(16) float sm[4][16 * CHK];
    const int tid = threadIdx.x;
    const int wi = tid >> 5, ln = tid & 31;
    const int q = wi & 3, g = wi >> 2;
    const int b0 = q * 4, ng = g * 8;
    const int nb = blockIdx.x * 16;
    const int dq = blockIdx.y;
    const int dbase = dq * (NCHK * CHK);

    auto stage = [&](int c) {
        const int d0 = dbase + c * CHK;
        #pragma unroll
        for (int k2 = 0; k2 < 2; k2++) {
            int fidx = tid + (k2 << 8);
            int nn = fidx >> 5, c4 = fidx & 31;
            const float* src = mem + (size_t)(nb + nn) * D_TOT + d0 + (c4 << 2);
            unsigned dst = (unsigned)__cvta_generic_to_shared(
                &sm[c & 3][nn * CHK + (c4 << 2)]);
            asm volatile("cp.async.cg.shared.global [%0], [%1], 16;" ::
                         "r"(dst), "l"(src));
        }
    };

    stage(0); asm volatile("cp.async.commit_group;" ::: "memory");
    stage(1); asm volatile("cp.async.commit_group;" ::: "memory");
    stage(2); asm volatile("cp.async.commit_group;" ::: "memory");

    unsigned long long acc[4][8];
    #pragma unroll
    for (int i = 0; i < 4; i++)
        #pragma unroll
        for (int j = 0; j < 8; j++) acc[i][j] = 0ull;
    unsigned long long na[2] = {0ull, 0ull};

    const int col = ln << 2;

    for (int c = 0; c < NCHK; c++) {
        asm volatile("cp.async.wait_group 2;" ::: "memory");
        __syncthreads();
        const float* smc = sm[c & 3];

        ulonglong2 m8[8];
        #pragma unroll
        for (int nn = 0; nn < 8; nn++)
            m8[nn] = *reinterpret_cast<const ulonglong2*>(smc + (ng + nn) * CHK + col);

        const int dg = dbase + c * CHK + col;
        #pragma unroll
        for (int bb = 0; bb < 4; bb++) {
            ulonglong2 k2 = *reinterpret_cast<const ulonglong2*>(
                key + (size_t)(b0 + bb) * D_TOT + dg);
            #pragma unroll
            for (int nn = 0; nn < 8; nn++) {
                ffma2(acc[bb][nn], m8[nn].x, k2.x);
                ffma2(acc[bb][nn], m8[nn].y, k2.y);
            }
        }
        // norms: warp q covers nn = 2q, 2q+1 of its octet
        #pragma unroll
        for (int j = 0; j < 2; j++) {
            ffma2(na[j], m8[2 * q + j].x, m8[2 * q + j].x);
            ffma2(na[j], m8[2 * q + j].y, m8[2 * q + j].y);
        }

        __syncthreads();
        if (c + 3 < NCHK) stage(c + 3);
        asm volatile("cp.async.commit_group;" ::: "memory");
    }

    // lane reductions (lanes partitioned d)
    #pragma unroll
    for (int bb = 0; bb < 4; bb++) {
        #pragma unroll
        for (int nn = 0; nn < 8; nn++) {
            float v = psum2(acc[bb][nn]);
            #pragma unroll
            for (int o = 16; o > 0; o >>= 1) v += __shfl_xor_sync(0xffffffffu, v, o);
            if (ln == 0)
                g_dotp[dq][b0 + bb][nb + ng + nn] = v;
        }
    }
    #pragma unroll
    for (int j = 0; j < 2; j++) {
        float v = psum2(na[j]);
        #pragma unroll
        for (int o = 16; o > 0; o >>= 1) v += __shfl_xor_sync(0xffffffffu, v, o);
        if (ln == 0 && q * 4 < 16)  // every warp writes its two n
            g_mn2p[dq][nb + ng + 2 * q + j] = v;
    }
}

// ================= kernel C: softmax of tan(cos * PI/2) =================
__global__ void k_softmax() {
    const int b = blockIdx.x;
    __shared__ float lg[N_TOT];
    __shared__ float red[32];
    const float knr = g_knr[b];
    const int tid = threadIdx.x;

    float mx = -1e30f;
    for (int n = tid; n < N_TOT; n += blockDim.x) {
        float dot = 0.f, mn2 = 0.f;
        #pragma unroll
        for (int dq = 0; dq < DQ; dq++) {
            dot += g_dotp[dq][b][n];
            mn2 += g_mn2p[dq][n];
        }
        float cs = dot / (knr * sqrtf(mn2));
        float l = tanf(cs * PI2C);
        lg[n] = l;
        mx = fmaxf(mx, l);
    }
    #pragma unroll
    for (int o = 16; o > 0; o >>= 1) mx = fmaxf(mx, __shfl_xor_sync(0xffffffffu, mx, o));
    if ((tid & 31) == 0) red[tid >> 5] = mx;
    __syncthreads();
    if (tid == 0) {
        float t = -1e30f;
        for (int w = 0; w < (int)(blockDim.x >> 5); w++) t = fmaxf(t, red[w]);
        red[0] = t;
    }
    __syncthreads();
    mx = red[0];
    __syncthreads();

    float s = 0.f;
    for (int n = tid; n < N_TOT; n += blockDim.x) {
        float e = expf(lg[n] - mx);
        lg[n] = e;
        s += e;
    }
    #pragma unroll
    for (int o = 16; o > 0; o >>= 1) s += __shfl_xor_sync(0xffffffffu, s, o);
    if ((tid & 31) == 0) red[tid >> 5] = s;
    __syncthreads();
    if (tid == 0) {
        float t = 0.f;
        for (int w = 0; w < (int)(blockDim.x >> 5); w++) t += red[w];
        red[0] = t;
    }
    __syncthreads();
    const float inv = 1.f / red[0];
    for (int n = tid; n < N_TOT; n += blockDim.x)
        g_wT[(size_t)n * B_SZ + b] = lg[n] * inv;
}

// ================= kernel D: weighted read (pass 2) =================
// grid (49, NS), 128 threads, 4 CTAs/SM. Block = 512 d x 125 n.
// FFMA2 inner loop; 5-deep LDG batching for MLP.
__global__ void __launch_bounds__(128, 4) k_read(const float* __restrict__ mem) {
    const int db = blockIdx.x, ns = blockIdx.y;
    const int n0 = ns * (N_TOT / NS);             // 125 n each
    const int tid = threadIdx.x;
    const int d = db * 512 + tid * 4;

    __shared__ __align__(16) float sw[(N_TOT / NS) * B_SZ];  // 125*16
    for (int i = tid; i < (N_TOT / NS) * B_SZ; i += blockDim.x)
        sw[i] = g_wT[(size_t)n0 * B_SZ + i];
    __syncthreads();

    unsigned long long acc[32];   // 16 b x 2 d-pairs
    #pragma unroll
    for (int i = 0; i < 32; i++) acc[i] = 0ull;

    const float* mp = mem + (size_t)n0 * D_TOT + d;

    #pragma unroll 1
    for (int n5 = 0; n5 < N_TOT / NS; n5 += 5) {
        ulonglong2 mreg[5];
        #pragma unroll
        for (int j = 0; j < 5; j++)
            mreg[j] = *reinterpret_cast<const ulonglong2*>(mp + (size_t)(n5 + j) * D_TOT);
        #pragma unroll
        for (int j = 0; j < 5; j++) {
            const float4* wv = reinterpret_cast<const float4*>(sw + ((n5 + j) << 4));
            float w[16];
            float4 w0 = wv[0], w1 = wv[1], w2 = wv[2], w3 = wv[3];
            w[0]=w0.x; w[1]=w0.y; w[2]=w0.z; w[3]=w0.w;
            w[4]=w1.x; w[5]=w1.y; w[6]=w1.z; w[7]=w1.w;
            w[8]=w2.x; w[9]=w2.y; w[10]=w2.z; w[11]=w2.w;
            w[12]=w3.x; w[13]=w3.y; w[14]=w3.z; w[15]=w3.w;
            #pragma unroll
            for (int bb = 0; bb < 16; bb++) {
                unsigned long long wp = dup2(w[bb]);
                ffma2(acc[2 * bb],     wp, mreg[j].x);
                ffma2(acc[2 * bb + 1], wp, mreg[j].y);
            }
        }
    }

    float* pp = g_part[ns];
    #pragma unroll
    for (int bb = 0; bb < 16; bb++) {
        ulonglong2 v; v.x = acc[2 * bb]; v.y = acc[2 * bb + 1];
        *reinterpret_cast<ulonglong2*>(pp + (size_t)bb * D_TOT + d) = v;
    }
}

// ================= kernel E: sum partials =================
__global__ void k_final(float* __restrict__ out) {
    const int i = blockIdx.x * blockDim.x + threadIdx.x;  // float4 index
    float4 s = make_float4(0.f, 0.f, 0.f, 0.f);
    #pragma unroll
    for (int p = 0; p < NS; p++) {
        float4 v = reinterpret_cast<const float4*>(g_part[p])[i];
        s.x += v.x; s.y += v.y; s.z += v.z; s.w += v.w;
    }
    reinterpret_cast<float4*>(out)[i] = s;
}

// ================= launcher =================
extern "C" void kernel_launch(void* const* d_in, const int* in_sizes, int n_in,
                              void* d_out, int out_size) {
    const float* key = (const float*)d_in[0];
    const float* mem = (const float*)d_in[1];
    if (n_in >= 2 && in_sizes[0] > in_sizes[1]) {  // defensive: key is the small one
        const float* t = key; key = mem; mem = t;
    }
    k_knorm<<<B_SZ, 256>>>(key);
    k_pass1<<<dim3(N_TOT / 16, DQ), 256>>>(key, mem);
    k_softmax<<<B_SZ, 256>>>();
    k_read<<<dim3(D_TOT / 512, NS), 128>>>(mem);
    k_final<<<(B_SZ * D_TOT / 4) / 256, 256>>>((float*)d_out);
}

// round 4
// speedup vs baseline: 1.2252x; 1.1992x over previous
#include <cuda_runtime.h>
#include <math.h>

#define D_TOT 25088      // 512*7*7
#define B_SZ  16
#define N_TOT 2000
#define NS    12         // n-splits for pass 2 (588 blocks = 1 full wave @4 CTA/SM)
#define DQ    7          // d-segments for pass 1
#define CHK   128        // floats per pass-1 chunk
#define NCHK  28         // chunks per d-segment (7*28*128 = 25088)
#define STG   6          // pass-1 pipeline stages
#define KSEG  4          // knorm segments
#define PI2C  (3.14159f * 0.5f)

// ---- scratch ----
__device__ float g_kn2p[KSEG][B_SZ];                  // partial ||key||^2
__device__ float g_dotp[DQ][B_SZ][N_TOT];             // partial dots
__device__ float g_mn2p[DQ][N_TOT];                   // partial ||m_n||^2
__device__ unsigned long long g_wT2[N_TOT * B_SZ];    // weights, dup-packed [n][b]
__device__ float g_part[NS][B_SZ * D_TOT];            // pass-2 partials

// ---- packed fp32x2 helpers ----
__device__ __forceinline__ void ffma2(unsigned long long& acc,
                                      unsigned long long a, unsigned long long b) {
    asm("fma.rn.f32x2 %0, %1, %2, %0;" : "+l"(acc) : "l"(a), "l"(b));
}
__device__ __forceinline__ unsigned long long dup2(float v) {
    unsigned long long r;
    asm("mov.b64 %0, {%1, %1};" : "=l"(r) : "r"(__float_as_uint(v)));
    return r;
}
__device__ __forceinline__ float psum2(unsigned long long v) {
    float lo, hi;
    asm("mov.b64 {%0, %1}, %2;" : "=f"(lo), "=f"(hi) : "l"(v));
    return lo + hi;
}

// ================= kernel A: key norm partials =================
__global__ void k_knorm(const float* __restrict__ key) {
    const int b = blockIdx.x >> 2, seg = blockIdx.x & 3;
    const int len = D_TOT / 4 / KSEG;                 // float4 count per seg (1568)
    const float4* kp = reinterpret_cast<const float4*>(key + (size_t)b * D_TOT)
                       + seg * len;
    float s = 0.f;
    for (int i = threadIdx.x; i < len; i += blockDim.x) {
        float4 v = kp[i];
        s += v.x * v.x + v.y * v.y + v.z * v.z + v.w * v.w;
    }
    __shared__ float red[8];
    #pragma unroll
    for (int o = 16; o > 0; o >>= 1) s += __shfl_xor_sync(0xffffffffu, s, o);
    if ((threadIdx.x & 31) == 0) red[threadIdx.x >> 5] = s;
    __syncthreads();
    if (threadIdx.x == 0) {
        float t = 0.f;
        for (int w = 0; w < (int)(blockDim.x >> 5); w++) t += red[w];
        g_kn2p[seg][b] = t;
    }
}

// ================= kernel B: dots + memory norms (pass 1) =================
// grid (125, 7). 256 threads = 8 warps: q=wi&3 -> 4 b each; g=wi>>2 -> 8 n each.
// 6-stage cp.async ring (depth 5), single sync per chunk, FFMA2.
__global__ void __launch_bounds__(256, 2) k_pass1(const float* __restrict__ key,
                                                  const float* __restrict__ mem) {
    __shared__ __align__(16) float sm[STG][16 * CHK];   // 48KB
    const int tid = threadIdx.x;
    const int wi = tid >> 5, ln = tid & 31;
    const int q = wi & 3, g = wi >> 2;
    const int b0 = q * 4, ng = g * 8;
    const int nb = blockIdx.x * 16;
    const int dq = blockIdx.y;
    const int dbase = dq * (NCHK * CHK);

    // per-thread fixed staging slot: thread covers (nn, c4) twice
    auto stage = [&](int c) {
        const int d0 = dbase + c * CHK;
        float* buf = sm[c % STG];
        #pragma unroll
        for (int k2 = 0; k2 < 2; k2++) {
            int fidx = tid + (k2 << 8);
            int nn = fidx >> 5, c4 = fidx & 31;
            const float* src = mem + (size_t)(nb + nn) * D_TOT + d0 + (c4 << 2);
            unsigned dst = (unsigned)__cvta_generic_to_shared(&buf[nn * CHK + (c4 << 2)]);
            asm volatile("cp.async.cg.shared.global [%0], [%1], 16;" ::
                         "r"(dst), "l"(src));
        }
        asm volatile("cp.async.commit_group;" ::: "memory");
    };

    #pragma unroll
    for (int c = 0; c < 5; c++) stage(c);

    unsigned long long acc[4][8];
    #pragma unroll
    for (int i = 0; i < 4; i++)
        #pragma unroll
        for (int j = 0; j < 8; j++) acc[i][j] = 0ull;
    unsigned long long na0 = 0ull, na1 = 0ull;

    const int col = ln << 2;

    for (int c = 0; c < NCHK; c++) {
        asm volatile("cp.async.wait_group 4;" ::: "memory");
        __syncthreads();
        const float* smc = sm[c % STG];

        const int dg = dbase + c * CHK + col;
        ulonglong2 k2[4];
        #pragma unroll
        for (int bb = 0; bb < 4; bb++)
            k2[bb] = *reinterpret_cast<const ulonglong2*>(
                key + (size_t)(b0 + bb) * D_TOT + dg);

        #pragma unroll
        for (int nn = 0; nn < 8; nn++) {
            ulonglong2 m = *reinterpret_cast<const ulonglong2*>(
                smc + (ng + nn) * CHK + col);
            #pragma unroll
            for (int bb = 0; bb < 4; bb++) {
                ffma2(acc[bb][nn], m.x, k2[bb].x);
                ffma2(acc[bb][nn], m.y, k2[bb].y);
            }
            if (nn == 2 * q)     { ffma2(na0, m.x, m.x); ffma2(na0, m.y, m.y); }
            if (nn == 2 * q + 1) { ffma2(na1, m.x, m.x); ffma2(na1, m.y, m.y); }
        }

        if (c + 5 < NCHK) stage(c + 5);   // writes buf (c+5)%6 == (c-1)%6, safe post-sync
    }

    // lane reductions (lanes partitioned d)
    #pragma unroll
    for (int bb = 0; bb < 4; bb++) {
        #pragma unroll
        for (int nn = 0; nn < 8; nn++) {
            float v = psum2(acc[bb][nn]);
            #pragma unroll
            for (int o = 16; o > 0; o >>= 1) v += __shfl_xor_sync(0xffffffffu, v, o);
            if (ln == 0) g_dotp[dq][b0 + bb][nb + ng + nn] = v;
        }
    }
    {
        float v0 = psum2(na0), v1 = psum2(na1);
        #pragma unroll
        for (int o = 16; o > 0; o >>= 1) {
            v0 += __shfl_xor_sync(0xffffffffu, v0, o);
            v1 += __shfl_xor_sync(0xffffffffu, v1, o);
        }
        if (ln == 0) {
            g_mn2p[dq][nb + ng + 2 * q]     = v0;
            g_mn2p[dq][nb + ng + 2 * q + 1] = v1;
        }
    }
}

// ================= kernel C: softmax of tan(cos * PI/2) =================
__global__ void k_softmax() {
    const int b = blockIdx.x;
    __shared__ float lg[N_TOT];
    __shared__ float red[32];
    const int tid = threadIdx.x;

    float kn2 = 0.f;
    #pragma unroll
    for (int s = 0; s < KSEG; s++) kn2 += g_kn2p[s][b];
    const float knr = sqrtf(kn2);

    float mx = -1e30f;
    for (int n = tid; n < N_TOT; n += blockDim.x) {
        float dot = 0.f, mn2 = 0.f;
        #pragma unroll
        for (int dq = 0; dq < DQ; dq++) {
            dot += g_dotp[dq][b][n];
            mn2 += g_mn2p[dq][n];
        }
        float cs = dot / (knr * sqrtf(mn2));
        float l = tanf(cs * PI2C);
        lg[n] = l;
        mx = fmaxf(mx, l);
    }
    #pragma unroll
    for (int o = 16; o > 0; o >>= 1) mx = fmaxf(mx, __shfl_xor_sync(0xffffffffu, mx, o));
    if ((tid & 31) == 0) red[tid >> 5] = mx;
    __syncthreads();
    if (tid == 0) {
        float t = -1e30f;
        for (int w = 0; w < (int)(blockDim.x >> 5); w++) t = fmaxf(t, red[w]);
        red[0] = t;
    }
    __syncthreads();
    mx = red[0];
    __syncthreads();

    float s = 0.f;
    for (int n = tid; n < N_TOT; n += blockDim.x) {
        float e = expf(lg[n] - mx);
        lg[n] = e;
        s += e;
    }
    #pragma unroll
    for (int o = 16; o > 0; o >>= 1) s += __shfl_xor_sync(0xffffffffu, s, o);
    if ((tid & 31) == 0) red[tid >> 5] = s;
    __syncthreads();
    if (tid == 0) {
        float t = 0.f;
        for (int w = 0; w < (int)(blockDim.x >> 5); w++) t += red[w];
        red[0] = t;
    }
    __syncthreads();
    const float inv = 1.f / red[0];
    for (int n = tid; n < N_TOT; n += blockDim.x)
        g_wT2[(size_t)n * B_SZ + b] = dup2(lg[n] * inv);
}

// ================= kernel D: weighted read (pass 2) =================
// grid (49, NS=12), 128 threads, 4 CTAs/SM => 588 blocks = 1 full wave.
// Pre-dup'ed packed weights; explicit 4-deep double-buffered prefetch.
__global__ void __launch_bounds__(128, 4) k_read(const float* __restrict__ mem) {
    const int db = blockIdx.x, ns = blockIdx.y;
    const int n0  = ns * 166 + min(ns, 8);
    const int len = 166 + (ns < 8 ? 1 : 0);           // 167 x8, 166 x4 = 2000
    const int tid = threadIdx.x;
    const int d = db * 512 + tid * 4;

    __shared__ __align__(16) unsigned long long sw[167 * B_SZ];  // dup-packed
    {
        const ulonglong2* src = reinterpret_cast<const ulonglong2*>(
            g_wT2 + (size_t)n0 * B_SZ);
        ulonglong2* dst = reinterpret_cast<ulonglong2*>(sw);
        for (int i = tid; i < len * (B_SZ / 2); i += blockDim.x) dst[i] = src[i];
    }
    __syncthreads();

    unsigned long long acc[32];
    #pragma unroll
    for (int i = 0; i < 32; i++) acc[i] = 0ull;

    const float* mp = mem + (size_t)n0 * D_TOT + d;
    const int ngrp = len >> 2, rem = len & 3;

    ulonglong2 A[4], Bb[4];
    #pragma unroll
    for (int j = 0; j < 4; j++)
        A[j] = *reinterpret_cast<const ulonglong2*>(mp + (size_t)j * D_TOT);

    for (int gI = 0; gI < ngrp; gI++) {
        const int nbase = gI << 2;
        // prefetch next group
        if (gI + 1 < ngrp) {
            #pragma unroll
            for (int j = 0; j < 4; j++)
                Bb[j] = *reinterpret_cast<const ulonglong2*>(
                    mp + (size_t)(nbase + 4 + j) * D_TOT);
        }
        #pragma unroll
        for (int j = 0; j < 4; j++) {
            const unsigned long long* wv = sw + ((nbase + j) << 4);
            #pragma unroll
            for (int bb = 0; bb < 16; bb++) {
                unsigned long long wp = wv[bb];
                ffma2(acc[2 * bb],     wp, A[j].x);
                ffma2(acc[2 * bb + 1], wp, A[j].y);
            }
        }
        #pragma unroll
        for (int j = 0; j < 4; j++) A[j] = Bb[j];
    }
    // tail
    for (int n = ngrp << 2; n < len; n++) {
        ulonglong2 m = *reinterpret_cast<const ulonglong2*>(mp + (size_t)n * D_TOT);
        const unsigned long long* wv = sw + (n << 4);
        #pragma unroll
        for (int bb = 0; bb < 16; bb++) {
            unsigned long long wp = wv[bb];
            ffma2(acc[2 * bb],     wp, m.x);
            ffma2(acc[2 * bb + 1], wp, m.y);
        }
    }

    float* pp = g_part[ns];
    #pragma unroll
    for (int bb = 0; bb < 16; bb++) {
        ulonglong2 v; v.x = acc[2 * bb]; v.y = acc[2 * bb + 1];
        *reinterpret_cast<ulonglong2*>(pp + (size_t)bb * D_TOT + d) = v;
    }
}

// ================= kernel E: sum partials =================
__global__ void k_final(float* __restrict__ out) {
    const int i = blockIdx.x * blockDim.x + threadIdx.x;  // float4 index
    float4 s = make_float4(0.f, 0.f, 0.f, 0.f);
    #pragma unroll
    for (int p = 0; p < NS; p++) {
        float4 v = reinterpret_cast<const float4*>(g_part[p])[i];
        s.x += v.x; s.y += v.y; s.z += v.z; s.w += v.w;
    }
    reinterpret_cast<float4*>(out)[i] = s;
}

// ================= launcher =================
extern "C" void kernel_launch(void* const* d_in, const int* in_sizes, int n_in,
                              void* d_out, int out_size) {
    const float* key = (const float*)d_in[0];
    const float* mem = (const float*)d_in[1];
    if (n_in >= 2 && in_sizes[0] > in_sizes[1]) {
        const float* t = key; key = mem; mem = t;
    }
    k_knorm<<<B_SZ * KSEG, 256>>>(key);
    k_pass1<<<dim3(N_TOT / 16, DQ), 256>>>(key, mem);
    k_softmax<<<B_SZ, 256>>>();
    k_read<<<dim3(D_TOT / 512, NS), 128>>>(mem);
    k_final<<<(B_SZ * D_TOT / 4) / 256, 256>>>((float*)d_out);
}

// round 5
// speedup vs baseline: 1.3615x; 1.1112x over previous
#include <cuda_runtime.h>
#include <math.h>

#define D_TOT 25088      // 512*7*7
#define B_SZ  16
#define N_TOT 2000
#define NS    12         // n-splits for pass 2
#define DQ    7          // d-segments for pass 1
#define CHK   128        // floats per pass-1 chunk
#define NCHK  28         // chunks per d-segment (7*28*128 = 25088)
#define STG   6          // pass-1 pipeline stages
#define KSEG  4          // knorm segments
#define PI2C  (3.14159f * 0.5f)

// ---- scratch ----
__device__ float g_kn2p[KSEG][B_SZ];                  // partial ||key||^2
__device__ float g_dotp[DQ][B_SZ][N_TOT];             // partial dots
__device__ float g_mn2p[DQ][N_TOT];                   // partial ||m_n||^2
__device__ unsigned long long g_wT2[N_TOT * B_SZ];    // weights, dup-packed [n][b]
__device__ float g_part[NS][B_SZ * D_TOT];            // pass-2 partials

// ---- packed fp32x2 helpers ----
__device__ __forceinline__ void ffma2(unsigned long long& acc,
                                      unsigned long long a, unsigned long long b) {
    asm("fma.rn.f32x2 %0, %1, %2, %0;" : "+l"(acc) : "l"(a), "l"(b));
}
__device__ __forceinline__ unsigned long long dup2(float v) {
    unsigned long long r;
    asm("mov.b64 %0, {%1, %1};" : "=l"(r) : "r"(__float_as_uint(v)));
    return r;
}
__device__ __forceinline__ float psum2(unsigned long long v) {
    float lo, hi;
    asm("mov.b64 {%0, %1}, %2;" : "=f"(lo), "=f"(hi) : "l"(v));
    return lo + hi;
}

// ================= kernel A: key norm partials =================
__global__ void k_knorm(const float* __restrict__ key) {
    const int b = blockIdx.x >> 2, seg = blockIdx.x & 3;
    const int len = D_TOT / 4 / KSEG;
    const float4* kp = reinterpret_cast<const float4*>(key + (size_t)b * D_TOT)
                       + seg * len;
    float s = 0.f;
    for (int i = threadIdx.x; i < len; i += blockDim.x) {
        float4 v = kp[i];
        s += v.x * v.x + v.y * v.y + v.z * v.z + v.w * v.w;
    }
    __shared__ float red[8];
    #pragma unroll
    for (int o = 16; o > 0; o >>= 1) s += __shfl_xor_sync(0xffffffffu, s, o);
    if ((threadIdx.x & 31) == 0) red[threadIdx.x >> 5] = s;
    __syncthreads();
    if (threadIdx.x == 0) {
        float t = 0.f;
        for (int w = 0; w < (int)(blockDim.x >> 5); w++) t += red[w];
        g_kn2p[seg][b] = t;
    }
}

// ================= kernel B: dots + memory norms (pass 1) =================
// grid (125, 7). 256 threads = 8 warps: q=wi&3 -> 4 b; g=wi>>2 -> 8 n.
// 6-stage cp.async ring for m; k prefetched one chunk ahead in registers.
__global__ void __launch_bounds__(256, 2) k_pass1(const float* __restrict__ key,
                                                  const float* __restrict__ mem) {
    __shared__ __align__(16) float sm[STG][16 * CHK];   // 48KB
    const int tid = threadIdx.x;
    const int wi = tid >> 5, ln = tid & 31;
    const int q = wi & 3, g = wi >> 2;
    const int b0 = q * 4, ng = g * 8;
    const int nb = blockIdx.x * 16;
    const int dq = blockIdx.y;
    const int dbase = dq * (NCHK * CHK);

    auto stage = [&](int c) {
        const int d0 = dbase + c * CHK;
        float* buf = sm[c % STG];
        #pragma unroll
        for (int k2i = 0; k2i < 2; k2i++) {
            int fidx = tid + (k2i << 8);
            int nn = fidx >> 5, c4 = fidx & 31;
            const float* src = mem + (size_t)(nb + nn) * D_TOT + d0 + (c4 << 2);
            unsigned dst = (unsigned)__cvta_generic_to_shared(&buf[nn * CHK + (c4 << 2)]);
            asm volatile("cp.async.cg.shared.global [%0], [%1], 16;" ::
                         "r"(dst), "l"(src));
        }
        asm volatile("cp.async.commit_group;" ::: "memory");
    };

    #pragma unroll
    for (int c = 0; c < 5; c++) stage(c);

    unsigned long long acc[4][8];
    #pragma unroll
    for (int i = 0; i < 4; i++)
        #pragma unroll
        for (int j = 0; j < 8; j++) acc[i][j] = 0ull;
    unsigned long long na0 = 0ull, na1 = 0ull;

    const int col = ln << 2;

    // k prefetch: registers hold chunk c's keys, loaded during chunk c-1
    ulonglong2 k2[4];
    #pragma unroll
    for (int bb = 0; bb < 4; bb++)
        k2[bb] = *reinterpret_cast<const ulonglong2*>(
            key + (size_t)(b0 + bb) * D_TOT + dbase + col);

    for (int c = 0; c < NCHK; c++) {
        asm volatile("cp.async.wait_group 4;" ::: "memory");
        __syncthreads();
        const float* smc = sm[c % STG];

        // prefetch k for next chunk (clamped; extra load of last chunk is harmless)
        const int cn = (c + 1 < NCHK) ? c + 1 : c;
        const int dgn = dbase + cn * CHK + col;
        ulonglong2 k2n[4];
        #pragma unroll
        for (int bb = 0; bb < 4; bb++)
            k2n[bb] = *reinterpret_cast<const ulonglong2*>(
                key + (size_t)(b0 + bb) * D_TOT + dgn);

        #pragma unroll
        for (int nn = 0; nn < 8; nn++) {
            ulonglong2 m = *reinterpret_cast<const ulonglong2*>(
                smc + (ng + nn) * CHK + col);
            #pragma unroll
            for (int bb = 0; bb < 4; bb++) {
                ffma2(acc[bb][nn], m.x, k2[bb].x);
                ffma2(acc[bb][nn], m.y, k2[bb].y);
            }
            if (nn == 2 * q)     { ffma2(na0, m.x, m.x); ffma2(na0, m.y, m.y); }
            if (nn == 2 * q + 1) { ffma2(na1, m.x, m.x); ffma2(na1, m.y, m.y); }
        }

        #pragma unroll
        for (int bb = 0; bb < 4; bb++) k2[bb] = k2n[bb];

        if (c + 5 < NCHK) stage(c + 5);
    }

    #pragma unroll
    for (int bb = 0; bb < 4; bb++) {
        #pragma unroll
        for (int nn = 0; nn < 8; nn++) {
            float v = psum2(acc[bb][nn]);
            #pragma unroll
            for (int o = 16; o > 0; o >>= 1) v += __shfl_xor_sync(0xffffffffu, v, o);
            if (ln == 0) g_dotp[dq][b0 + bb][nb + ng + nn] = v;
        }
    }
    {
        float v0 = psum2(na0), v1 = psum2(na1);
        #pragma unroll
        for (int o = 16; o > 0; o >>= 1) {
            v0 += __shfl_xor_sync(0xffffffffu, v0, o);
            v1 += __shfl_xor_sync(0xffffffffu, v1, o);
        }
        if (ln == 0) {
            g_mn2p[dq][nb + ng + 2 * q]     = v0;
            g_mn2p[dq][nb + ng + 2 * q + 1] = v1;
        }
    }
}

// ================= kernel C: softmax of tan(cos * PI/2) =================
__global__ void k_softmax() {
    const int b = blockIdx.x;
    __shared__ float lg[N_TOT];
    __shared__ float red[32];
    const int tid = threadIdx.x;

    float kn2 = 0.f;
    #pragma unroll
    for (int s = 0; s < KSEG; s++) kn2 += g_kn2p[s][b];
    const float knr = sqrtf(kn2);

    float mx = -1e30f;
    for (int n = tid; n < N_TOT; n += blockDim.x) {
        float dot = 0.f, mn2 = 0.f;
        #pragma unroll
        for (int dq = 0; dq < DQ; dq++) {
            dot += g_dotp[dq][b][n];
            mn2 += g_mn2p[dq][n];
        }
        float cs = dot / (knr * sqrtf(mn2));
        float l = tanf(cs * PI2C);
        lg[n] = l;
        mx = fmaxf(mx, l);
    }
    #pragma unroll
    for (int o = 16; o > 0; o >>= 1) mx = fmaxf(mx, __shfl_xor_sync(0xffffffffu, mx, o));
    if ((tid & 31) == 0) red[tid >> 5] = mx;
    __syncthreads();
    if (tid == 0) {
        float t = -1e30f;
        for (int w = 0; w < (int)(blockDim.x >> 5); w++) t = fmaxf(t, red[w]);
        red[0] = t;
    }
    __syncthreads();
    mx = red[0];
    __syncthreads();

    float s = 0.f;
    for (int n = tid; n < N_TOT; n += blockDim.x) {
        float e = expf(lg[n] - mx);
        lg[n] = e;
        s += e;
    }
    #pragma unroll
    for (int o = 16; o > 0; o >>= 1) s += __shfl_xor_sync(0xffffffffu, s, o);
    if ((tid & 31) == 0) red[tid >> 5] = s;
    __syncthreads();
    if (tid == 0) {
        float t = 0.f;
        for (int w = 0; w < (int)(blockDim.x >> 5); w++) t += red[w];
        red[0] = t;
    }
    __syncthreads();
    const float inv = 1.f / red[0];
    for (int n = tid; n < N_TOT; n += blockDim.x)
        g_wT2[(size_t)n * B_SZ + b] = dup2(lg[n] * inv);
}

// ================= kernel D: weighted read (pass 2) =================
// grid (49, NS=12), 128 threads. Weights read as ulonglong2 (LDS.128 broadcast,
// 2 packed weights per instr). 4-deep LDG batches; no forced occupancy.
__global__ void __launch_bounds__(128) k_read(const float* __restrict__ mem) {
    const int db = blockIdx.x, ns = blockIdx.y;
    const int n0  = ns * 166 + min(ns, 8);
    const int len = 166 + (ns < 8 ? 1 : 0);           // 167 x8, 166 x4 = 2000
    const int tid = threadIdx.x;
    const int d = db * 512 + tid * 4;

    __shared__ __align__(16) ulonglong2 sw2[167 * (B_SZ / 2)];  // [n][8 pairs]
    {
        const ulonglong2* src = reinterpret_cast<const ulonglong2*>(
            g_wT2 + (size_t)n0 * B_SZ);
        for (int i = tid; i < len * (B_SZ / 2); i += blockDim.x) sw2[i] = src[i];
    }
    __syncthreads();

    unsigned long long acc[32];   // [b][2 d-pairs]
    #pragma unroll
    for (int i = 0; i < 32; i++) acc[i] = 0ull;

    const float* mp = mem + (size_t)n0 * D_TOT + d;
    const int ngrp = len >> 2;

    for (int gI = 0; gI < ngrp; gI++) {
        const int nbase = gI << 2;
        ulonglong2 mr[4];
        #pragma unroll
        for (int j = 0; j < 4; j++)
            mr[j] = *reinterpret_cast<const ulonglong2*>(
                mp + (size_t)(nbase + j) * D_TOT);
        #pragma unroll
        for (int j = 0; j < 4; j++) {
            const ulonglong2* wp = sw2 + (nbase + j) * (B_SZ / 2);
            #pragma unroll
            for (int p = 0; p < 8; p++) {
                ulonglong2 wv = wp[p];                 // weights b=2p, b=2p+1
                ffma2(acc[4 * p],     wv.x, mr[j].x);
                ffma2(acc[4 * p + 1], wv.x, mr[j].y);
                ffma2(acc[4 * p + 2], wv.y, mr[j].x);
                ffma2(acc[4 * p + 3], wv.y, mr[j].y);
            }
        }
    }
    // tail (len % 4 = 2 or 3)
    for (int n = ngrp << 2; n < len; n++) {
        ulonglong2 m = *reinterpret_cast<const ulonglong2*>(mp + (size_t)n * D_TOT);
        const ulonglong2* wp = sw2 + n * (B_SZ / 2);
        #pragma unroll
        for (int p = 0; p < 8; p++) {
            ulonglong2 wv = wp[p];
            ffma2(acc[4 * p],     wv.x, m.x);
            ffma2(acc[4 * p + 1], wv.x, m.y);
            ffma2(acc[4 * p + 2], wv.y, m.x);
            ffma2(acc[4 * p + 3], wv.y, m.y);
        }
    }

    float* pp = g_part[ns];
    #pragma unroll
    for (int p = 0; p < 8; p++) {
        ulonglong2 v0; v0.x = acc[4 * p];     v0.y = acc[4 * p + 1];
        ulonglong2 v1; v1.x = acc[4 * p + 2]; v1.y = acc[4 * p + 3];
        *reinterpret_cast<ulonglong2*>(pp + (size_t)(2 * p)     * D_TOT + d) = v0;
        *reinterpret_cast<ulonglong2*>(pp + (size_t)(2 * p + 1) * D_TOT + d) = v1;
    }
}

// ================= kernel E: sum partials =================
__global__ void k_final(float* __restrict__ out) {
    const int i = blockIdx.x * blockDim.x + threadIdx.x;  // float4 index
    float4 s = make_float4(0.f, 0.f, 0.f, 0.f);
    #pragma unroll
    for (int p = 0; p < NS; p++) {
        float4 v = reinterpret_cast<const float4*>(g_part[p])[i];
        s.x += v.x; s.y += v.y; s.z += v.z; s.w += v.w;
    }
    reinterpret_cast<float4*>(out)[i] = s;
}

// ================= launcher =================
extern "C" void kernel_launch(void* const* d_in, const int* in_sizes, int n_in,
                              void* d_out, int out_size) {
    const float* key = (const float*)d_in[0];
    const float* mem = (const float*)d_in[1];
    if (n_in >= 2 && in_sizes[0] > in_sizes[1]) {
        const float* t = key; key = mem; mem = t;
    }
    k_knorm<<<B_SZ * KSEG, 256>>>(key);
    k_pass1<<<dim3(N_TOT / 16, DQ), 256>>>(key, mem);
    k_softmax<<<B_SZ, 256>>>();
    k_read<<<dim3(D_TOT / 512, NS), 128>>>(mem);
    k_final<<<(B_SZ * D_TOT / 4) / 256, 256>>>((float*)d_out);
}

// round 6
// speedup vs baseline: 1.3747x; 1.0097x over previous
#include <cuda_runtime.h>
#include <math.h>

#define D_TOT 25088      // 512*7*7
#define B_SZ  16
#define N_TOT 2000
#define NS    12         // n-splits for pass 2
#define DQ    7          // d-segments for pass 1
#define CHK   128        // floats per pass-1 chunk
#define NCHK  28         // chunks per d-segment (7*28*128 = 25088)
#define STG   6          // pass-1 pipeline stages
#define KSEG  4          // knorm segments
#define PI2C  (3.14159f * 0.5f)

// ---- scratch ----
__device__ float g_kn2p[KSEG][B_SZ];                  // partial ||key||^2
__device__ float g_dotp[DQ][B_SZ][N_TOT];             // partial dots
__device__ float g_mn2p[DQ][N_TOT];                   // partial ||m_n||^2
__device__ unsigned long long g_wT2[N_TOT * B_SZ];    // weights, dup-packed [n][b]
__device__ float g_part[NS][B_SZ * D_TOT];            // pass-2 partials

// ---- packed fp32x2 helpers ----
__device__ __forceinline__ void ffma2(unsigned long long& acc,
                                      unsigned long long a, unsigned long long b) {
    asm("fma.rn.f32x2 %0, %1, %2, %0;" : "+l"(acc) : "l"(a), "l"(b));
}
__device__ __forceinline__ unsigned long long dup2(float v) {
    unsigned long long r;
    asm("mov.b64 %0, {%1, %1};" : "=l"(r) : "r"(__float_as_uint(v)));
    return r;
}
__device__ __forceinline__ float psum2(unsigned long long v) {
    float lo, hi;
    asm("mov.b64 {%0, %1}, %2;" : "=f"(lo), "=f"(hi) : "l"(v));
    return lo + hi;
}

// ================= kernel A: key norm partials =================
__global__ void k_knorm(const float* __restrict__ key) {
    const int b = blockIdx.x >> 2, seg = blockIdx.x & 3;
    const int len = D_TOT / 4 / KSEG;
    const float4* kp = reinterpret_cast<const float4*>(key + (size_t)b * D_TOT)
                       + seg * len;
    float s = 0.f;
    for (int i = threadIdx.x; i < len; i += blockDim.x) {
        float4 v = kp[i];
        s += v.x * v.x + v.y * v.y + v.z * v.z + v.w * v.w;
    }
    __shared__ float red[8];
    #pragma unroll
    for (int o = 16; o > 0; o >>= 1) s += __shfl_xor_sync(0xffffffffu, s, o);
    if ((threadIdx.x & 31) == 0) red[threadIdx.x >> 5] = s;
    __syncthreads();
    if (threadIdx.x == 0) {
        float t = 0.f;
        for (int w = 0; w < (int)(blockDim.x >> 5); w++) t += red[w];
        g_kn2p[seg][b] = t;
    }
}

// ================= kernel B: dots + memory norms (pass 1) =================
// grid (125, 7). 256 threads = 8 warps: q=wi&3 -> 4 b; g=wi>>2 -> 8 n.
// 6-stage cp.async ring; ONE wait+sync per TWO chunks; k reg-prefetch.
__global__ void __launch_bounds__(256, 2) k_pass1(const float* __restrict__ key,
                                                  const float* __restrict__ mem) {
    __shared__ __align__(16) float sm[STG][16 * CHK];   // 48KB
    const int tid = threadIdx.x;
    const int wi = tid >> 5, ln = tid & 31;
    const int q = wi & 3, g = wi >> 2;
    const int b0 = q * 4, ng = g * 8;
    const int nb = blockIdx.x * 16;
    const int dq = blockIdx.y;
    const int dbase = dq * (NCHK * CHK);
    const int col = ln << 2;

    auto stage = [&](int c) {
        const int d0 = dbase + c * CHK;
        float* buf = sm[c % STG];
        #pragma unroll
        for (int k2i = 0; k2i < 2; k2i++) {
            int fidx = tid + (k2i << 8);
            int nn = fidx >> 5, c4 = fidx & 31;
            const float* src = mem + (size_t)(nb + nn) * D_TOT + d0 + (c4 << 2);
            unsigned dst = (unsigned)__cvta_generic_to_shared(&buf[nn * CHK + (c4 << 2)]);
            asm volatile("cp.async.cg.shared.global [%0], [%1], 16;" ::
                         "r"(dst), "l"(src));
        }
        asm volatile("cp.async.commit_group;" ::: "memory");
    };

    #pragma unroll
    for (int c = 0; c < 4; c++) stage(c);

    unsigned long long acc[4][8];
    #pragma unroll
    for (int i = 0; i < 4; i++)
        #pragma unroll
        for (int j = 0; j < 8; j++) acc[i][j] = 0ull;
    unsigned long long na0 = 0ull, na1 = 0ull;

    // k prefetch: registers hold chunk c's keys, loaded during chunk c-1
    ulonglong2 k2[4];
    #pragma unroll
    for (int bb = 0; bb < 4; bb++)
        k2[bb] = *reinterpret_cast<const ulonglong2*>(
            key + (size_t)(b0 + bb) * D_TOT + dbase + col);

    auto compute_chunk = [&](int c) {
        const float* smc = sm[c % STG];
        const int cn = (c + 1 < NCHK) ? c + 1 : c;
        const int dgn = dbase + cn * CHK + col;
        ulonglong2 k2n[4];
        #pragma unroll
        for (int bb = 0; bb < 4; bb++)
            k2n[bb] = *reinterpret_cast<const ulonglong2*>(
                key + (size_t)(b0 + bb) * D_TOT + dgn);

        #pragma unroll
        for (int nn = 0; nn < 8; nn++) {
            ulonglong2 m = *reinterpret_cast<const ulonglong2*>(
                smc + (ng + nn) * CHK + col);
            #pragma unroll
            for (int bb = 0; bb < 4; bb++) {
                ffma2(acc[bb][nn], m.x, k2[bb].x);
                ffma2(acc[bb][nn], m.y, k2[bb].y);
            }
            if (nn == 2 * q)     { ffma2(na0, m.x, m.x); ffma2(na0, m.y, m.y); }
            if (nn == 2 * q + 1) { ffma2(na1, m.x, m.x); ffma2(na1, m.y, m.y); }
        }
        #pragma unroll
        for (int bb = 0; bb < 4; bb++) k2[bb] = k2n[bb];
    };

    for (int p = 0; p < NCHK / 2; p++) {
        const int c0 = 2 * p;
        asm volatile("cp.async.wait_group 2;" ::: "memory");
        __syncthreads();
        // buffers (c0+4)%6=(c0-2)%6 and (c0+5)%6=(c0-1)%6 were consumed in the
        // previous pair iteration; this sync orders that — safe to restage now.
        if (c0 + 4 < NCHK) stage(c0 + 4);
        if (c0 + 5 < NCHK) stage(c0 + 5);
        compute_chunk(c0);
        compute_chunk(c0 + 1);
    }

    #pragma unroll
    for (int bb = 0; bb < 4; bb++) {
        #pragma unroll
        for (int nn = 0; nn < 8; nn++) {
            float v = psum2(acc[bb][nn]);
            #pragma unroll
            for (int o = 16; o > 0; o >>= 1) v += __shfl_xor_sync(0xffffffffu, v, o);
            if (ln == 0) g_dotp[dq][b0 + bb][nb + ng + nn] = v;
        }
    }
    {
        float v0 = psum2(na0), v1 = psum2(na1);
        #pragma unroll
        for (int o = 16; o > 0; o >>= 1) {
            v0 += __shfl_xor_sync(0xffffffffu, v0, o);
            v1 += __shfl_xor_sync(0xffffffffu, v1, o);
        }
        if (ln == 0) {
            g_mn2p[dq][nb + ng + 2 * q]     = v0;
            g_mn2p[dq][nb + ng + 2 * q + 1] = v1;
        }
    }
}

// ================= kernel C: softmax of tan(cos * PI/2) =================
__global__ void k_softmax() {
    const int b = blockIdx.x;
    __shared__ float lg[N_TOT];
    __shared__ float red[32];
    const int tid = threadIdx.x;

    float kn2 = 0.f;
    #pragma unroll
    for (int s = 0; s < KSEG; s++) kn2 += g_kn2p[s][b];
    const float knr = sqrtf(kn2);

    float mx = -1e30f;
    for (int n = tid; n < N_TOT; n += blockDim.x) {
        float dot = 0.f, mn2 = 0.f;
        #pragma unroll
        for (int dq = 0; dq < DQ; dq++) {
            dot += g_dotp[dq][b][n];
            mn2 += g_mn2p[dq][n];
        }
        float cs = dot / (knr * sqrtf(mn2));
        float l = tanf(cs * PI2C);
        lg[n] = l;
        mx = fmaxf(mx, l);
    }
    #pragma unroll
    for (int o = 16; o > 0; o >>= 1) mx = fmaxf(mx, __shfl_xor_sync(0xffffffffu, mx, o));
    if ((tid & 31) == 0) red[tid >> 5] = mx;
    __syncthreads();
    if (tid == 0) {
        float t = -1e30f;
        for (int w = 0; w < (int)(blockDim.x >> 5); w++) t = fmaxf(t, red[w]);
        red[0] = t;
    }
    __syncthreads();
    mx = red[0];
    __syncthreads();

    float s = 0.f;
    for (int n = tid; n < N_TOT; n += blockDim.x) {
        float e = expf(lg[n] - mx);
        lg[n] = e;
        s += e;
    }
    #pragma unroll
    for (int o = 16; o > 0; o >>= 1) s += __shfl_xor_sync(0xffffffffu, s, o);
    if ((tid & 31) == 0) red[tid >> 5] = s;
    __syncthreads();
    if (tid == 0) {
        float t = 0.f;
        for (int w = 0; w < (int)(blockDim.x >> 5); w++) t += red[w];
        red[0] = t;
    }
    __syncthreads();
    const float inv = 1.f / red[0];
    for (int n = tid; n < N_TOT; n += blockDim.x)
        g_wT2[(size_t)n * B_SZ + b] = dup2(lg[n] * inv);
}

// ================= kernel D: weighted read (pass 2) =================
// grid (49, NS=12), 128 threads, 4 CTAs/SM. LDS.128 packed weights.
// Rotating register prefetch at distance 4: load n+4+j before computing n+j.
__global__ void __launch_bounds__(128, 4) k_read(const float* __restrict__ mem) {
    const int db = blockIdx.x, ns = blockIdx.y;
    const int n0  = ns * 166 + min(ns, 8);
    const int len = 166 + (ns < 8 ? 1 : 0);           // 167 x8, 166 x4 = 2000
    const int tid = threadIdx.x;
    const int d = db * 512 + tid * 4;

    __shared__ __align__(16) ulonglong2 sw2[167 * (B_SZ / 2)];  // [n][8 pairs]
    {
        const ulonglong2* src = reinterpret_cast<const ulonglong2*>(
            g_wT2 + (size_t)n0 * B_SZ);
        for (int i = tid; i < len * (B_SZ / 2); i += blockDim.x) sw2[i] = src[i];
    }
    __syncthreads();

    unsigned long long acc[32];   // [b][2 d-pairs]
    #pragma unroll
    for (int i = 0; i < 32; i++) acc[i] = 0ull;

    const float* mp = mem + (size_t)n0 * D_TOT + d;
    const int nfull = (len >> 2) << 2;                // groups of 4

    ulonglong2 mr[4];
    #pragma unroll
    for (int j = 0; j < 4; j++)
        mr[j] = *reinterpret_cast<const ulonglong2*>(mp + (size_t)j * D_TOT);

    for (int nb4 = 0; nb4 < nfull; nb4 += 4) {
        #pragma unroll
        for (int j = 0; j < 4; j++) {
            int pf = nb4 + 4 + j; if (pf >= len) pf = len - 1;   // clamped prefetch
            ulonglong2 nx = *reinterpret_cast<const ulonglong2*>(
                mp + (size_t)pf * D_TOT);
            const ulonglong2* wp = sw2 + (nb4 + j) * (B_SZ / 2);
            #pragma unroll
            for (int p = 0; p < 8; p++) {
                ulonglong2 wv = wp[p];                 // weights b=2p, b=2p+1
                ffma2(acc[4 * p],     wv.x, mr[j].x);
                ffma2(acc[4 * p + 1], wv.x, mr[j].y);
                ffma2(acc[4 * p + 2], wv.y, mr[j].x);
                ffma2(acc[4 * p + 3], wv.y, mr[j].y);
            }
            mr[j] = nx;
        }
    }
    // tail (len % 4 = 2 or 3): data already sits in mr[0..rem-1] via prefetch
    for (int n = nfull; n < len; n++) {
        ulonglong2 m = mr[n - nfull];
        const ulonglong2* wp = sw2 + n * (B_SZ / 2);
        #pragma unroll
        for (int p = 0; p < 8; p++) {
            ulonglong2 wv = wp[p];
            ffma2(acc[4 * p],     wv.x, m.x);
            ffma2(acc[4 * p + 1], wv.x, m.y);
            ffma2(acc[4 * p + 2], wv.y, m.x);
            ffma2(acc[4 * p + 3], wv.y, m.y);
        }
    }

    float* pp = g_part[ns];
    #pragma unroll
    for (int p = 0; p < 8; p++) {
        ulonglong2 v0; v0.x = acc[4 * p];     v0.y = acc[4 * p + 1];
        ulonglong2 v1; v1.x = acc[4 * p + 2]; v1.y = acc[4 * p + 3];
        *reinterpret_cast<ulonglong2*>(pp + (size_t)(2 * p)     * D_TOT + d) = v0;
        *reinterpret_cast<ulonglong2*>(pp + (size_t)(2 * p + 1) * D_TOT + d) = v1;
    }
}

// ================= kernel E: sum partials =================
__global__ void k_final(float* __restrict__ out) {
    const int i = blockIdx.x * blockDim.x + threadIdx.x;  // float4 index
    float4 s = make_float4(0.f, 0.f, 0.f, 0.f);
    #pragma unroll
    for (int p = 0; p < NS; p++) {
        float4 v = reinterpret_cast<const float4*>(g_part[p])[i];
        s.x += v.x; s.y += v.y; s.z += v.z; s.w += v.w;
    }
    reinterpret_cast<float4*>(out)[i] = s;
}

// ================= launcher =================
extern "C" void kernel_launch(void* const* d_in, const int* in_sizes, int n_in,
                              void* d_out, int out_size) {
    const float* key = (const float*)d_in[0];
    const float* mem = (const float*)d_in[1];
    if (n_in >= 2 && in_sizes[0] > in_sizes[1]) {
        const float* t = key; key = mem; mem = t;
    }
    k_knorm<<<B_SZ * KSEG, 256>>>(key);
    k_pass1<<<dim3(N_TOT / 16, DQ), 256>>>(key, mem);
    k_softmax<<<B_SZ, 256>>>();
    k_read<<<dim3(D_TOT / 512, NS), 128>>>(mem);
    k_final<<<(B_SZ * D_TOT / 4) / 256, 256>>>((float*)d_out);
}